// round 2
// baseline (speedup 1.0000x reference)
#include <cuda_runtime.h>
#include <cuda_bf16.h>
#include <math.h>

// Shapes (fixed for this problem)
//   x:            (4, 256, 64, 64)  fp32
//   conv_offset_w:(27, 256, 3, 3)   fp32
//   conv_offset_b:(27,)             fp32
//   dcn_weight:   (256, 256, 3, 3)  fp32
//   out:          (4, 256, 64, 64)  fp32
//
// Pipeline:
//   K1 conv_offset  -> g_om   [4][27][64][64]
//   K2 permute      -> g_wperm[k=kk*256+c][o]           (2304 x 256)
//   K3 sample       -> g_valT [k=kk*256+c][m=n*4096+p]  (2304 x 16384)
//   K4 sgemm        -> out[n][o][p] = sum_k valT[k][m] * wperm[k][o]

#define NN 4
#define CC 256
#define HH 64
#define WW 64
#define OC 256
#define KDIM 2304          // 9 * 256
#define MDIM 16384         // 4 * 64 * 64

__device__ float g_om[NN * 27 * HH * WW];            // 1.77 MB
__device__ float g_wperm[KDIM * OC];                 // 2.36 MB
__device__ float g_valT[(size_t)KDIM * MDIM];        // 151 MB

// ---------------------------------------------------------------------------
// K1: offset conv. grid (64 y, 4 n), 256 threads = 64 pixels x 4 channel-groups
// ---------------------------------------------------------------------------
__global__ __launch_bounds__(256) void conv_offset_kernel(
    const float* __restrict__ x, const float* __restrict__ w,
    const float* __restrict__ b)
{
    int y = blockIdx.x, n = blockIdx.y;
    int t = threadIdx.x;
    int p = t & 63, g = t >> 6;

    __shared__ __align__(16) float sm[6912];
    float* xs = sm;         // [4][3][66] = 792 (padded region to 800)
    float* ws = sm + 800;   // [4][27][12] = 1296

    float acc[27];
#pragma unroll
    for (int oc = 0; oc < 27; oc++) acc[oc] = 0.f;

    for (int i = 0; i < 64; i++) {
        // stage x rows y-1..y+1 for the 4 channels {i, 64+i, 128+i, 192+i}
        for (int idx = t; idx < 792; idx += 256) {
            int gg = idx / 198, rem = idx - gg * 198;
            int r = rem / 66, j = rem - r * 66;
            int yy = y + r - 1, xx = j - 1;
            float v = 0.f;
            if (yy >= 0 && yy < HH && xx >= 0 && xx < WW)
                v = x[(((size_t)(n * CC + gg * 64 + i) * HH) + yy) * WW + xx];
            xs[(gg * 3 + r) * 66 + j] = v;
        }
        // stage weights for those channels: [g][oc][12] (9 used, 12 for f4 align)
        for (int idx = t; idx < 972; idx += 256) {
            int gg = idx / 243, rem = idx - gg * 243;
            int oc = rem / 9, kq = rem - oc * 9;
            ws[(gg * 27 + oc) * 12 + kq] = w[(oc * CC + gg * 64 + i) * 9 + kq];
        }
        __syncthreads();

        float tv[9];
#pragma unroll
        for (int r = 0; r < 3; r++)
#pragma unroll
            for (int s = 0; s < 3; s++)
                tv[r * 3 + s] = xs[(g * 3 + r) * 66 + p + s];

        const float4* wsg = (const float4*)(ws + g * 27 * 12);
#pragma unroll
        for (int oc = 0; oc < 27; oc++) {
            float4 w0 = wsg[oc * 3 + 0];
            float4 w1 = wsg[oc * 3 + 1];
            float  w8 = ws[(g * 27 + oc) * 12 + 8];
            acc[oc] += tv[0] * w0.x + tv[1] * w0.y + tv[2] * w0.z + tv[3] * w0.w
                     + tv[4] * w1.x + tv[5] * w1.y + tv[6] * w1.z + tv[7] * w1.w
                     + tv[8] * w8;
        }
        __syncthreads();
    }

    // cross-group reduction through smem (aliases xs/ws, safe after sync)
    float* red = sm;  // [4*64][27] = 6912
#pragma unroll
    for (int oc = 0; oc < 27; oc++) red[(g * 64 + p) * 27 + oc] = acc[oc];
    __syncthreads();
    for (int idx = t; idx < 1728; idx += 256) {
        int p2 = idx / 27, oc = idx - p2 * 27;
        float s = red[p2 * 27 + oc] + red[(64 + p2) * 27 + oc]
                + red[(128 + p2) * 27 + oc] + red[(192 + p2) * 27 + oc] + b[oc];
        g_om[(((size_t)n * 27 + oc) * HH + y) * WW + p2] = s;
    }
}

// ---------------------------------------------------------------------------
// K2: permute dcn_weight (o,c,kk) -> wperm[k=kk*256+c][o]
// ---------------------------------------------------------------------------
__global__ __launch_bounds__(256) void permute_w_kernel(const float* __restrict__ dw)
{
    int t = blockIdx.x * 256 + threadIdx.x;   // t = k*256 + o
    int o = t & 255;
    int k = t >> 8;
    int c = k & 255;
    int kk = k >> 8;
    g_wperm[t] = dw[(o * CC + c) * 9 + kk];
}

// ---------------------------------------------------------------------------
// K3: deformable bilinear sampling -> g_valT[k][m]
// grid (64 y, 4 n), 256 threads = 64 pixels x 4 channel-groups
// ---------------------------------------------------------------------------
__global__ __launch_bounds__(256) void sample_kernel(const float* __restrict__ x)
{
    int y = blockIdx.x, n = blockIdx.y;
    int t = threadIdx.x;

    __shared__ __align__(16) int   soff[576][4];
    __shared__ __align__(16) float swt[576][4];

    // Phase A: per (pixel, kk) tap metadata: 4 clamped tap offsets + 4
    // mask-folded bilinear weights (0 for out-of-image taps).
    for (int idx = t; idx < 576; idx += 256) {
        int p = idx / 9, kk = idx - p * 9;
        const float* omn = g_om + (size_t)n * 27 * 4096 + y * 64 + p;
        float oy = omn[(size_t)(2 * kk) * 4096];
        float ox = omn[(size_t)(2 * kk + 1) * 4096];
        float mv = omn[(size_t)(18 + kk) * 4096];
        float m  = 1.f / (1.f + __expf(-mv));

        float py = (float)(y + kk / 3) + oy;          // base(y+1) + inner(ky-1)
        float px = (float)(p + (kk % 3)) + ox;        // base(p+1) + inner(kx-1)
        py = fminf(fmaxf(py, 0.f), 65.f);
        px = fminf(fmaxf(px, 0.f), 65.f);
        float fy = floorf(py), fx = floorf(px);
        int y1 = (int)fy, x1 = (int)fx;
        float ly = py - fy, lx = px - fx;
        float hy = 1.f - ly, hx = 1.f - lx;
        float wt0 = hy * hx, wt1 = hy * lx, wt2 = ly * hx, wt3 = ly * lx;

#pragma unroll
        for (int q = 0; q < 4; q++) {
            int Y = y1 + (q >> 1);
            int X = x1 + (q & 1);
            bool valid = (Y >= 1 && Y <= 64 && X >= 1 && X <= 64);
            int Yc = min(max(Y, 1), 64), Xc = min(max(X, 1), 64);
            float wq = (q == 0) ? wt0 : (q == 1) ? wt1 : (q == 2) ? wt2 : wt3;
            soff[idx][q] = (Yc - 1) * 64 + (Xc - 1);
            swt[idx][q]  = valid ? wq * m : 0.f;
        }
    }
    __syncthreads();

    // Phase B: lanes over pixels (coalesced loads AND stores); metadata hoisted
    // to registers (channel-independent).
    int p = t & 63, g = t >> 6;
    int   ro[36];
    float rw[36];
#pragma unroll
    for (int kk = 0; kk < 9; kk++) {
        int4   o4 = *(const int4*)  &soff[p * 9 + kk][0];
        float4 w4 = *(const float4*)&swt [p * 9 + kk][0];
        ro[kk * 4 + 0] = o4.x; ro[kk * 4 + 1] = o4.y;
        ro[kk * 4 + 2] = o4.z; ro[kk * 4 + 3] = o4.w;
        rw[kk * 4 + 0] = w4.x; rw[kk * 4 + 1] = w4.y;
        rw[kk * 4 + 2] = w4.z; rw[kk * 4 + 3] = w4.w;
    }

    size_t mbase = (size_t)n * 4096 + (size_t)y * 64 + p;
    for (int j = 0; j < 64; j++) {
        int c = g * 64 + j;
        const float* xb = x + ((size_t)(n * CC + c)) * 4096;
        float* vb = g_valT + (size_t)c * MDIM + mbase;
#pragma unroll
        for (int kk = 0; kk < 9; kk++) {
            float v = rw[kk * 4 + 0] * __ldg(&xb[ro[kk * 4 + 0]])
                    + rw[kk * 4 + 1] * __ldg(&xb[ro[kk * 4 + 1]])
                    + rw[kk * 4 + 2] * __ldg(&xb[ro[kk * 4 + 2]])
                    + rw[kk * 4 + 3] * __ldg(&xb[ro[kk * 4 + 3]]);
            vb[(size_t)kk * 256 * MDIM] = v;
        }
    }
}

// ---------------------------------------------------------------------------
// K4: SGEMM  C[m][o] = sum_k valT[k][m] * wperm[k][o]
// BM=128, BN=64, BK=16, 256 threads, 8x4 micro-tile
// ---------------------------------------------------------------------------
__global__ __launch_bounds__(256) void sgemm_kernel(float* __restrict__ out)
{
    __shared__ __align__(16) float As[16][128];
    __shared__ __align__(16) float Bs[16][64];

    int t = threadIdx.x;
    int m0 = blockIdx.x * 128, o0 = blockIdx.y * 64;
    int tm = t >> 4, tn = t & 15;

    float acc[8][4];
#pragma unroll
    for (int i = 0; i < 8; i++)
#pragma unroll
        for (int j = 0; j < 4; j++) acc[i][j] = 0.f;

    int ar0 = t >> 5;            // rows 0..7
    int ac  = (t & 31) * 4;
    int ar1 = ar0 + 8;           // rows 8..15
    int br  = t >> 4;            // 0..15
    int bc  = (t & 15) * 4;

    for (int k0 = 0; k0 < KDIM; k0 += 16) {
        *(float4*)&As[ar0][ac] = *(const float4*)&g_valT[(size_t)(k0 + ar0) * MDIM + m0 + ac];
        *(float4*)&As[ar1][ac] = *(const float4*)&g_valT[(size_t)(k0 + ar1) * MDIM + m0 + ac];
        *(float4*)&Bs[br][bc]  = *(const float4*)&g_wperm[(size_t)(k0 + br) * OC + o0 + bc];
        __syncthreads();
#pragma unroll
        for (int kk = 0; kk < 16; kk++) {
            float a[8], bb[4];
            *(float4*)&a[0] = *(const float4*)&As[kk][tm * 8];
            *(float4*)&a[4] = *(const float4*)&As[kk][tm * 8 + 4];
            *(float4*)&bb[0] = *(const float4*)&Bs[kk][tn * 4];
#pragma unroll
            for (int i = 0; i < 8; i++)
#pragma unroll
                for (int j = 0; j < 4; j++)
                    acc[i][j] += a[i] * bb[j];
        }
        __syncthreads();
    }

    int mbase = m0 + tm * 8;
#pragma unroll
    for (int i = 0; i < 8; i++) {
        int m = mbase + i;
        int n = m >> 12, mp = m & 4095;
        float* op = out + ((size_t)n * OC) * 4096 + mp;
#pragma unroll
        for (int j = 0; j < 4; j++)
            op[(size_t)(o0 + tn * 4 + j) * 4096] = acc[i][j];
    }
}

// ---------------------------------------------------------------------------
extern "C" void kernel_launch(void* const* d_in, const int* in_sizes, int n_in,
                              void* d_out, int out_size)
{
    const float* x      = (const float*)d_in[0];
    const float* conv_w = (const float*)d_in[1];
    const float* conv_b = (const float*)d_in[2];
    const float* dcn_w  = (const float*)d_in[3];
    float* out = (float*)d_out;

    conv_offset_kernel<<<dim3(64, 4), 256>>>(x, conv_w, conv_b);
    permute_w_kernel<<<KDIM, 256>>>(dcn_w);
    sample_kernel<<<dim3(64, 4), 256>>>(x);
    sgemm_kernel<<<dim3(MDIM / 128, OC / 64), 256>>>(out);
}